// round 1
// baseline (speedup 1.0000x reference)
#include <cuda_runtime.h>
#include <math.h>

#define S_LEN   4096
#define DMODEL  2048
#define NH      16
#define NKV     4
#define HD      128
#define KV_DIM  512   // NKV*HD

// Scratch (allocation-free rule: __device__ globals)
__device__ float g_q[S_LEN * DMODEL];
__device__ float g_k[S_LEN * KV_DIM];
__device__ float g_v[S_LEN * KV_DIM];
__device__ float g_att[S_LEN * DMODEL];

// ---------------------------------------------------------------------------
// SGEMM: C[M,N] = A[M,K] @ B[K,N], all row-major, M%128==0, N%128==0, K%16==0
// 128x128 tile, BK=16, 256 threads, 8x8 register blocking.
// ---------------------------------------------------------------------------
__global__ __launch_bounds__(256) void sgemm_kernel(
    const float* __restrict__ A, const float* __restrict__ B,
    float* __restrict__ C, int M, int N, int K)
{
    __shared__ float As[16][132];   // transposed tile: As[k][m]
    __shared__ float Bs[16][132];   // Bs[k][n]

    const int tid = threadIdx.x;
    const int ty  = tid >> 4;       // 0..15
    const int tx  = tid & 15;       // 0..15
    const int bm  = blockIdx.y * 128;
    const int bn  = blockIdx.x * 128;

    float acc[8][8];
    #pragma unroll
    for (int i = 0; i < 8; i++)
        #pragma unroll
        for (int j = 0; j < 8; j++) acc[i][j] = 0.0f;

    const float* Aptr = A + (size_t)bm * K;
    const float* Bptr = B + bn;

    for (int k0 = 0; k0 < K; k0 += 16) {
        // Load A tile 128x16, store transposed
        #pragma unroll
        for (int s = 0; s < 2; s++) {
            int u   = tid + s * 256;          // 0..511 float4 units
            int row = u >> 2;                 // 0..127
            int k4  = u & 3;                  // 0..3
            float4 v = *(const float4*)(Aptr + (size_t)row * K + k0 + k4 * 4);
            As[k4*4+0][row] = v.x;
            As[k4*4+1][row] = v.y;
            As[k4*4+2][row] = v.z;
            As[k4*4+3][row] = v.w;
        }
        // Load B tile 16x128
        #pragma unroll
        for (int s = 0; s < 2; s++) {
            int u  = tid + s * 256;
            int kr = u >> 5;                  // 0..15
            int c4 = u & 31;                  // 0..31
            *(float4*)(&Bs[kr][c4 * 4]) =
                *(const float4*)(Bptr + (size_t)(k0 + kr) * N + c4 * 4);
        }
        __syncthreads();

        #pragma unroll
        for (int kk = 0; kk < 16; kk++) {
            float a[8], b[8];
            *(float4*)(a)     = *(const float4*)(&As[kk][ty * 8]);
            *(float4*)(a + 4) = *(const float4*)(&As[kk][ty * 8 + 4]);
            *(float4*)(b)     = *(const float4*)(&Bs[kk][tx * 8]);
            *(float4*)(b + 4) = *(const float4*)(&Bs[kk][tx * 8 + 4]);
            #pragma unroll
            for (int i = 0; i < 8; i++)
                #pragma unroll
                for (int j = 0; j < 8; j++)
                    acc[i][j] = fmaf(a[i], b[j], acc[i][j]);
        }
        __syncthreads();
    }

    #pragma unroll
    for (int i = 0; i < 8; i++) {
        float* cp = C + (size_t)(bm + ty * 8 + i) * N + bn + tx * 8;
        *(float4*)(cp)     = make_float4(acc[i][0], acc[i][1], acc[i][2], acc[i][3]);
        *(float4*)(cp + 4) = make_float4(acc[i][4], acc[i][5], acc[i][6], acc[i][7]);
    }
}

// ---------------------------------------------------------------------------
// RoPE (in-place on g_q and g_k). Each thread handles one (d, d+64) pair.
// cos/sin are [S, 128] with cos[s,d] == cos[s,d+64].
// ---------------------------------------------------------------------------
__global__ void rope_kernel(const float* __restrict__ cos_t,
                            const float* __restrict__ sin_t)
{
    const int NQ = S_LEN * NH  * 64;   // 4096*1024
    const int NK = S_LEN * NKV * 64;   // 4096*256
    int idx = blockIdx.x * blockDim.x + threadIdx.x;
    if (idx < NQ) {
        int s   = idx >> 10;
        int rem = idx & 1023;
        int h   = rem >> 6;
        int d   = rem & 63;
        float c  = cos_t[s * HD + d];
        float sn = sin_t[s * HD + d];
        float* p = g_q + (size_t)s * DMODEL + h * HD + d;
        float x0 = p[0], x1 = p[64];
        p[0]  = x0 * c - x1 * sn;
        p[64] = x1 * c + x0 * sn;
    } else if (idx < NQ + NK) {
        int j   = idx - NQ;
        int s   = j >> 8;
        int rem = j & 255;
        int h   = rem >> 6;
        int d   = rem & 63;
        float c  = cos_t[s * HD + d];
        float sn = sin_t[s * HD + d];
        float* p = g_k + (size_t)s * KV_DIM + h * HD + d;
        float x0 = p[0], x1 = p[64];
        p[0]  = x0 * c - x1 * sn;
        p[64] = x1 * c + x0 * sn;
    }
}

// ---------------------------------------------------------------------------
// Flash attention, fp32, causal, GQA. Grid: (S/64, NH). 256 threads.
// BM=64 q rows, BN=64 keys/iter, d=128.
// smem: Qs[64][129], Ks[64][129], Vs[64][132], Ps[64][65]  = 116480 B dynamic
// ---------------------------------------------------------------------------
#define QS_STRIDE 129
#define VS_STRIDE 132
#define PS_STRIDE 65
#define ATT_SMEM_FLOATS (64*QS_STRIDE*2 + 64*VS_STRIDE + 64*PS_STRIDE)

__global__ __launch_bounds__(256) void attn_kernel()
{
    extern __shared__ float sm[];
    float* Qs = sm;                            // [64][129]
    float* Ks = Qs + 64 * QS_STRIDE;           // [64][129]
    float* Vs = Ks + 64 * QS_STRIDE;           // [64][132]
    float* Ps = Vs + 64 * VS_STRIDE;           // [64][65]

    const int qt  = blockIdx.x;
    const int h   = blockIdx.y;
    const int kvh = h >> 2;

    const int tid = threadIdx.x;
    const int ty  = tid >> 4;       // 0..15
    const int tx  = tid & 15;       // 0..15
    const int r0  = ty * 4;         // S rows / O rows owned
    const int c0  = tx * 4;         // S cols owned
    const int oc0 = tx * 8;         // O cols owned

    const float scale = 0.08838834764831845f;  // 1/sqrt(128)

    // Load Q tile (scaled)
    for (int u = tid; u < 64 * 32; u += 256) {
        int row = u >> 5, c4 = u & 31;
        float4 v = *(const float4*)(g_q + (size_t)(qt * 64 + row) * DMODEL + h * HD + c4 * 4);
        float* qp = Qs + row * QS_STRIDE + c4 * 4;
        qp[0] = v.x * scale; qp[1] = v.y * scale;
        qp[2] = v.z * scale; qp[3] = v.w * scale;
    }

    float O[4][8];
    #pragma unroll
    for (int i = 0; i < 4; i++)
        #pragma unroll
        for (int c = 0; c < 8; c++) O[i][c] = 0.0f;
    float m_i[4] = {-INFINITY, -INFINITY, -INFINITY, -INFINITY};
    float l_i[4] = {0.0f, 0.0f, 0.0f, 0.0f};

    for (int jt = 0; jt <= qt; jt++) {
        __syncthreads();   // previous PV reads of Vs/Ps complete
        // Load K, V tiles
        for (int u = tid; u < 64 * 32; u += 256) {
            int row = u >> 5, c4 = u & 31;
            size_t goff = (size_t)(jt * 64 + row) * KV_DIM + kvh * HD + c4 * 4;
            float4 kv = *(const float4*)(g_k + goff);
            float* kp = Ks + row * QS_STRIDE + c4 * 4;
            kp[0] = kv.x; kp[1] = kv.y; kp[2] = kv.z; kp[3] = kv.w;
            float4 vv = *(const float4*)(g_v + goff);
            *(float4*)(Vs + row * VS_STRIDE + c4 * 4) = vv;
        }
        __syncthreads();

        // S = Qs @ Ks^T  (4x4 per thread)
        float acc[4][4];
        #pragma unroll
        for (int i = 0; i < 4; i++)
            #pragma unroll
            for (int j = 0; j < 4; j++) acc[i][j] = 0.0f;

        #pragma unroll 4
        for (int kk = 0; kk < 128; kk++) {
            float a[4], b[4];
            #pragma unroll
            for (int i = 0; i < 4; i++) a[i] = Qs[(r0 + i) * QS_STRIDE + kk];
            #pragma unroll
            for (int j = 0; j < 4; j++) b[j] = Ks[(c0 + j) * QS_STRIDE + kk];
            #pragma unroll
            for (int i = 0; i < 4; i++)
                #pragma unroll
                for (int j = 0; j < 4; j++)
                    acc[i][j] = fmaf(a[i], b[j], acc[i][j]);
        }

        // Causal mask on the diagonal tile
        if (jt == qt) {
            #pragma unroll
            for (int i = 0; i < 4; i++)
                #pragma unroll
                for (int j = 0; j < 4; j++)
                    if (c0 + j > r0 + i) acc[i][j] = -INFINITY;
        }

        // Online softmax (row stats replicated across the 16 lanes of a half-warp)
        #pragma unroll
        for (int i = 0; i < 4; i++) {
            float mloc = fmaxf(fmaxf(acc[i][0], acc[i][1]), fmaxf(acc[i][2], acc[i][3]));
            #pragma unroll
            for (int off = 8; off >= 1; off >>= 1)
                mloc = fmaxf(mloc, __shfl_xor_sync(0xffffffffu, mloc, off));
            float mnew = fmaxf(m_i[i], mloc);
            float corr = __expf(m_i[i] - mnew);
            float ls = 0.0f;
            #pragma unroll
            for (int j = 0; j < 4; j++) {
                float p = __expf(acc[i][j] - mnew);
                acc[i][j] = p;
                ls += p;
            }
            #pragma unroll
            for (int off = 8; off >= 1; off >>= 1)
                ls += __shfl_xor_sync(0xffffffffu, ls, off);
            l_i[i] = l_i[i] * corr + ls;
            m_i[i] = mnew;
            #pragma unroll
            for (int c = 0; c < 8; c++) O[i][c] *= corr;
            #pragma unroll
            for (int j = 0; j < 4; j++)
                Ps[(r0 + i) * PS_STRIDE + c0 + j] = acc[i][j];
        }
        __syncthreads();   // Ps fully written

        // O += Ps @ Vs
        #pragma unroll 4
        for (int j = 0; j < 64; j++) {
            float4 v0 = *(const float4*)(Vs + j * VS_STRIDE + oc0);
            float4 v1 = *(const float4*)(Vs + j * VS_STRIDE + oc0 + 4);
            #pragma unroll
            for (int i = 0; i < 4; i++) {
                float p = Ps[(r0 + i) * PS_STRIDE + j];
                O[i][0] = fmaf(p, v0.x, O[i][0]);
                O[i][1] = fmaf(p, v0.y, O[i][1]);
                O[i][2] = fmaf(p, v0.z, O[i][2]);
                O[i][3] = fmaf(p, v0.w, O[i][3]);
                O[i][4] = fmaf(p, v1.x, O[i][4]);
                O[i][5] = fmaf(p, v1.y, O[i][5]);
                O[i][6] = fmaf(p, v1.z, O[i][6]);
                O[i][7] = fmaf(p, v1.w, O[i][7]);
            }
        }
    }

    // Normalize and write out
    #pragma unroll
    for (int i = 0; i < 4; i++) {
        float inv = 1.0f / l_i[i];
        float* op = g_att + (size_t)(qt * 64 + r0 + i) * DMODEL + h * HD + oc0;
        *(float4*)(op)     = make_float4(O[i][0]*inv, O[i][1]*inv, O[i][2]*inv, O[i][3]*inv);
        *(float4*)(op + 4) = make_float4(O[i][4]*inv, O[i][5]*inv, O[i][6]*inv, O[i][7]*inv);
    }
}

// ---------------------------------------------------------------------------
extern "C" void kernel_launch(void* const* d_in, const int* in_sizes, int n_in,
                              void* d_out, int out_size)
{
    const float* X    = (const float*)d_in[0];  // [1,4096,2048]
    const float* cosT = (const float*)d_in[1];  // [4096,128]
    const float* sinT = (const float*)d_in[2];  // [4096,128]
    const float* Wq   = (const float*)d_in[3];  // [2048,2048]
    const float* Wk   = (const float*)d_in[4];  // [2048,512]
    const float* Wv   = (const float*)d_in[5];  // [2048,512]
    const float* Wo   = (const float*)d_in[6];  // [2048,2048]
    float* out = (float*)d_out;                 // [1,4096,2048]

    // Resolve scratch symbols (non-stream API; safe under graph capture)
    float *pq = nullptr, *pk = nullptr, *pv = nullptr, *pa = nullptr;
    cudaGetSymbolAddress((void**)&pq, g_q);
    cudaGetSymbolAddress((void**)&pk, g_k);
    cudaGetSymbolAddress((void**)&pv, g_v);
    cudaGetSymbolAddress((void**)&pa, g_att);

    // Opt-in to >48KB dynamic smem for the attention kernel (idempotent)
    cudaFuncSetAttribute(attn_kernel, cudaFuncAttributeMaxDynamicSharedMemorySize,
                         ATT_SMEM_FLOATS * (int)sizeof(float));

    dim3 blk(256);

    // QKV projections
    sgemm_kernel<<<dim3(DMODEL / 128, S_LEN / 128), blk>>>(X, Wq, pq, S_LEN, DMODEL, DMODEL);
    sgemm_kernel<<<dim3(KV_DIM / 128, S_LEN / 128), blk>>>(X, Wk, pk, S_LEN, KV_DIM, DMODEL);
    sgemm_kernel<<<dim3(KV_DIM / 128, S_LEN / 128), blk>>>(X, Wv, pv, S_LEN, KV_DIM, DMODEL);

    // RoPE on Q and K (in place)
    {
        int total = S_LEN * NH * 64 + S_LEN * NKV * 64;
        rope_kernel<<<(total + 255) / 256, blk>>>(cosT, sinT);
    }

    // Attention
    attn_kernel<<<dim3(S_LEN / 64, NH), blk, ATT_SMEM_FLOATS * (int)sizeof(float)>>>();

    // Output projection
    sgemm_kernel<<<dim3(DMODEL / 128, S_LEN / 128), blk>>>(pa, Wo, out, S_LEN, DMODEL, DMODEL);
}

// round 4
// speedup vs baseline: 1.4470x; 1.4470x over previous
#include <cuda_runtime.h>
#include <math.h>
#include <stdint.h>

#define S_LEN   4096
#define DMODEL  2048
#define NH      16
#define NKV     4
#define HD      128
#define KV_DIM  512

// Scratch (allocation-free rule: __device__ globals)
__device__ float g_q[S_LEN * DMODEL];
__device__ float g_k[S_LEN * KV_DIM];
__device__ float g_v[S_LEN * KV_DIM];
__device__ float g_att[S_LEN * DMODEL];
__device__ float g_xr[S_LEN * DMODEL];      // tf32-rounded hidden states
__device__ float g_wqt[DMODEL * DMODEL];    // Wq^T [N,K]
__device__ float g_wkt[KV_DIM * DMODEL];
__device__ float g_wvt[KV_DIM * DMODEL];
__device__ float g_wot[DMODEL * DMODEL];

// ---------------------------------------------------------------------------
__device__ __forceinline__ float tf32r(float v) {
    asm("cvt.rna.tf32.f32 %0, %1;" : "=f"(v) : "f"(v));
    return v;
}

__device__ __forceinline__ uint32_t smem_u32(const void* p) {
    uint32_t a;
    asm("{ .reg .u64 t; cvta.to.shared.u64 t, %1; cvt.u32.u64 %0, t; }"
        : "=r"(a) : "l"(p));
    return a;
}

__device__ __forceinline__ void mma_tf32(float* c, const uint32_t* a, const uint32_t* b) {
    asm volatile("mma.sync.aligned.m16n8k8.row.col.f32.tf32.tf32.f32 "
        "{%0,%1,%2,%3}, {%4,%5,%6,%7}, {%8,%9}, {%0,%1,%2,%3};"
        : "+f"(c[0]), "+f"(c[1]), "+f"(c[2]), "+f"(c[3])
        : "r"(a[0]), "r"(a[1]), "r"(a[2]), "r"(a[3]), "r"(b[0]), "r"(b[1]));
}

// ---------------------------------------------------------------------------
// Weight transpose + tf32 round: dst[c][r] = tf32(src[r][c]); src is [R,C]
// ---------------------------------------------------------------------------
__global__ void transpose_round_kernel(const float* __restrict__ src,
                                       float* __restrict__ dst, int R, int C)
{
    __shared__ float t[32][33];
    int r0 = blockIdx.y * 32, c0 = blockIdx.x * 32;
    int x = threadIdx.x, y = threadIdx.y;  // 32 x 8
    #pragma unroll
    for (int i = y; i < 32; i += 8)
        t[i][x] = src[(size_t)(r0 + i) * C + c0 + x];
    __syncthreads();
    #pragma unroll
    for (int i = y; i < 32; i += 8)
        dst[(size_t)(c0 + i) * R + r0 + x] = tf32r(t[x][i]);
}

__global__ void round_x_kernel(const float4* __restrict__ src,
                               float4* __restrict__ dst, int n4)
{
    int i = blockIdx.x * blockDim.x + threadIdx.x;
    if (i < n4) {
        float4 v = src[i];
        v.x = tf32r(v.x); v.y = tf32r(v.y); v.z = tf32r(v.z); v.w = tf32r(v.w);
        dst[i] = v;
    }
}

// ---------------------------------------------------------------------------
// mma.sync tf32 GEMM: C[M,N] = A[M,K] @ Bt[N,K]^T (A, Bt row-major, tf32-valued)
// CTA 128x128, 8 warps (4x2), warp tile 32x64, KC=32 double-buffered cp.async.
// Smem layout: [128][36] floats per matrix (pad avoids bank conflicts).
// ---------------------------------------------------------------------------
#define KC 32
#define PADS 36
#define MAT_FLOATS (128 * PADS)           // 4608
#define STAGE_FLOATS (2 * MAT_FLOATS)     // 9216
#define GEMM_SMEM (2 * STAGE_FLOATS * 4)  // 73728 bytes

__global__ __launch_bounds__(256, 2) void mma_gemm_tf32(
    const float* __restrict__ A, const float* __restrict__ Bt,
    float* __restrict__ C, int K, int N)
{
    extern __shared__ __align__(16) float sm[];

    const int tid  = threadIdx.x;
    const int wid  = tid >> 5;
    const int lane = tid & 31;
    const int m0 = blockIdx.y * 128;
    const int n0 = blockIdx.x * 128;

    const int wm = (wid >> 1) * 32;   // warp row offset in tile
    const int wn = (wid & 1) * 64;    // warp col offset in tile

    const int NC = K >> 5;

    auto load_chunk = [&](int chunk, int stage) {
        int k0 = chunk << 5;
        float* sb = sm + stage * STAGE_FLOATS;
        #pragma unroll
        for (int p = 0; p < 8; p++) {
            int u = tid + (p << 8);       // 0..2047 16B units
            int isB = u >> 10;
            int v = u & 1023;
            int row = v >> 3;             // 0..127
            int c16 = v & 7;              // 16B unit in 32-float row
            const float* gp = (isB ? Bt + (size_t)(n0 + row) * K
                                   : A  + (size_t)(m0 + row) * K) + k0 + (c16 << 2);
            uint32_t sa = smem_u32(sb + isB * MAT_FLOATS + row * PADS + (c16 << 2));
            asm volatile("cp.async.cg.shared.global [%0], [%1], 16;"
                         :: "r"(sa), "l"(gp) : "memory");
        }
        asm volatile("cp.async.commit_group;" ::: "memory");
    };

    float acc[2][8][4];
    #pragma unroll
    for (int mi = 0; mi < 2; mi++)
        #pragma unroll
        for (int ni = 0; ni < 8; ni++)
            #pragma unroll
            for (int r = 0; r < 4; r++) acc[mi][ni][r] = 0.0f;

    load_chunk(0, 0);
    if (NC > 1) load_chunk(1, 1);

    const int lr = lane >> 2;   // 0..7
    const int lc = lane & 3;    // 0..3

    for (int i = 0; i < NC; i++) {
        int s = i & 1;
        if (i < NC - 1) asm volatile("cp.async.wait_group 1;" ::: "memory");
        else            asm volatile("cp.async.wait_group 0;" ::: "memory");
        __syncthreads();

        const float* As = sm + s * STAGE_FLOATS;
        const float* Bs = As + MAT_FLOATS;

        #pragma unroll
        for (int kk = 0; kk < 4; kk++) {
            int k = kk << 3;
            uint32_t a[2][4], b[8][2];
            #pragma unroll
            for (int mi = 0; mi < 2; mi++) {
                const float* ap = As + (wm + mi * 16 + lr) * PADS + k + lc;
                a[mi][0] = __float_as_uint(ap[0]);
                a[mi][1] = __float_as_uint(ap[8 * PADS]);
                a[mi][2] = __float_as_uint(ap[4]);
                a[mi][3] = __float_as_uint(ap[8 * PADS + 4]);
            }
            #pragma unroll
            for (int ni = 0; ni < 8; ni++) {
                const float* bp = Bs + (wn + ni * 8 + lr) * PADS + k + lc;
                b[ni][0] = __float_as_uint(bp[0]);
                b[ni][1] = __float_as_uint(bp[4]);
            }
            #pragma unroll
            for (int ni = 0; ni < 8; ni++)
                #pragma unroll
                for (int mi = 0; mi < 2; mi++)
                    mma_tf32(acc[mi][ni], a[mi], b[ni]);
        }
        __syncthreads();
        if (i + 2 < NC) load_chunk(i + 2, s);
    }

    // Epilogue: c0,c1 at (row, col..col+1); c2,c3 at (row+8, ...)
    #pragma unroll
    for (int mi = 0; mi < 2; mi++) {
        int row = m0 + wm + mi * 16 + lr;
        #pragma unroll
        for (int ni = 0; ni < 8; ni++) {
            int col = n0 + wn + ni * 8 + 2 * lc;
            *(float2*)(C + (size_t)row * N + col) =
                make_float2(acc[mi][ni][0], acc[mi][ni][1]);
            *(float2*)(C + (size_t)(row + 8) * N + col) =
                make_float2(acc[mi][ni][2], acc[mi][ni][3]);
        }
    }
}

// ---------------------------------------------------------------------------
// RoPE (in-place on g_q and g_k)
// ---------------------------------------------------------------------------
__global__ void rope_kernel(const float* __restrict__ cos_t,
                            const float* __restrict__ sin_t)
{
    const int NQ = S_LEN * NH  * 64;
    const int NK = S_LEN * NKV * 64;
    int idx = blockIdx.x * blockDim.x + threadIdx.x;
    if (idx < NQ) {
        int s   = idx >> 10;
        int rem = idx & 1023;
        int h   = rem >> 6;
        int d   = rem & 63;
        float c  = cos_t[s * HD + d];
        float sn = sin_t[s * HD + d];
        float* p = g_q + (size_t)s * DMODEL + h * HD + d;
        float x0 = p[0], x1 = p[64];
        p[0]  = x0 * c - x1 * sn;
        p[64] = x1 * c + x0 * sn;
    } else if (idx < NQ + NK) {
        int j   = idx - NQ;
        int s   = j >> 8;
        int rem = j & 255;
        int h   = rem >> 6;
        int d   = rem & 63;
        float c  = cos_t[s * HD + d];
        float sn = sin_t[s * HD + d];
        float* p = g_k + (size_t)s * KV_DIM + h * HD + d;
        float x0 = p[0], x1 = p[64];
        p[0]  = x0 * c - x1 * sn;
        p[64] = x1 * c + x0 * sn;
    }
}

// ---------------------------------------------------------------------------
// Flash attention, fp32, causal, GQA (SIMT; tf32-rounds its output for Wo MMA)
// ---------------------------------------------------------------------------
#define QS_STRIDE 129
#define VS_STRIDE 132
#define PS_STRIDE 65
#define ATT_SMEM_FLOATS (64*QS_STRIDE*2 + 64*VS_STRIDE + 64*PS_STRIDE)

__global__ __launch_bounds__(256) void attn_kernel()
{
    extern __shared__ float smf[];
    float* Qs = smf;
    float* Ks = Qs + 64 * QS_STRIDE;
    float* Vs = Ks + 64 * QS_STRIDE;
    float* Ps = Vs + 64 * VS_STRIDE;

    const int qt  = blockIdx.x;
    const int h   = blockIdx.y;
    const int kvh = h >> 2;

    const int tid = threadIdx.x;
    const int ty  = tid >> 4;
    const int tx  = tid & 15;
    const int r0  = ty * 4;
    const int c0  = tx * 4;
    const int oc0 = tx * 8;

    const float scale = 0.08838834764831845f;

    for (int u = tid; u < 64 * 32; u += 256) {
        int row = u >> 5, c4 = u & 31;
        float4 v = *(const float4*)(g_q + (size_t)(qt * 64 + row) * DMODEL + h * HD + c4 * 4);
        float* qp = Qs + row * QS_STRIDE + c4 * 4;
        qp[0] = v.x * scale; qp[1] = v.y * scale;
        qp[2] = v.z * scale; qp[3] = v.w * scale;
    }

    float O[4][8];
    #pragma unroll
    for (int i = 0; i < 4; i++)
        #pragma unroll
        for (int c = 0; c < 8; c++) O[i][c] = 0.0f;
    float m_i[4] = {-INFINITY, -INFINITY, -INFINITY, -INFINITY};
    float l_i[4] = {0.0f, 0.0f, 0.0f, 0.0f};

    for (int jt = 0; jt <= qt; jt++) {
        __syncthreads();
        for (int u = tid; u < 64 * 32; u += 256) {
            int row = u >> 5, c4 = u & 31;
            size_t goff = (size_t)(jt * 64 + row) * KV_DIM + kvh * HD + c4 * 4;
            float4 kv = *(const float4*)(g_k + goff);
            float* kp = Ks + row * QS_STRIDE + c4 * 4;
            kp[0] = kv.x; kp[1] = kv.y; kp[2] = kv.z; kp[3] = kv.w;
            float4 vv = *(const float4*)(g_v + goff);
            *(float4*)(Vs + row * VS_STRIDE + c4 * 4) = vv;
        }
        __syncthreads();

        float acc[4][4];
        #pragma unroll
        for (int i = 0; i < 4; i++)
            #pragma unroll
            for (int j = 0; j < 4; j++) acc[i][j] = 0.0f;

        #pragma unroll 4
        for (int kk = 0; kk < 128; kk++) {
            float a[4], b[4];
            #pragma unroll
            for (int i = 0; i < 4; i++) a[i] = Qs[(r0 + i) * QS_STRIDE + kk];
            #pragma unroll
            for (int j = 0; j < 4; j++) b[j] = Ks[(c0 + j) * QS_STRIDE + kk];
            #pragma unroll
            for (int i = 0; i < 4; i++)
                #pragma unroll
                for (int j = 0; j < 4; j++)
                    acc[i][j] = fmaf(a[i], b[j], acc[i][j]);
        }

        if (jt == qt) {
            #pragma unroll
            for (int i = 0; i < 4; i++)
                #pragma unroll
                for (int j = 0; j < 4; j++)
                    if (c0 + j > r0 + i) acc[i][j] = -INFINITY;
        }

        #pragma unroll
        for (int i = 0; i < 4; i++) {
            float mloc = fmaxf(fmaxf(acc[i][0], acc[i][1]), fmaxf(acc[i][2], acc[i][3]));
            #pragma unroll
            for (int off = 8; off >= 1; off >>= 1)
                mloc = fmaxf(mloc, __shfl_xor_sync(0xffffffffu, mloc, off));
            float mnew = fmaxf(m_i[i], mloc);
            float corr = __expf(m_i[i] - mnew);
            float ls = 0.0f;
            #pragma unroll
            for (int j = 0; j < 4; j++) {
                float p = __expf(acc[i][j] - mnew);
                acc[i][j] = p;
                ls += p;
            }
            #pragma unroll
            for (int off = 8; off >= 1; off >>= 1)
                ls += __shfl_xor_sync(0xffffffffu, ls, off);
            l_i[i] = l_i[i] * corr + ls;
            m_i[i] = mnew;
            #pragma unroll
            for (int c = 0; c < 8; c++) O[i][c] *= corr;
            #pragma unroll
            for (int j = 0; j < 4; j++)
                Ps[(r0 + i) * PS_STRIDE + c0 + j] = acc[i][j];
        }
        __syncthreads();

        #pragma unroll 4
        for (int j = 0; j < 64; j++) {
            float4 v0 = *(const float4*)(Vs + j * VS_STRIDE + oc0);
            float4 v1 = *(const float4*)(Vs + j * VS_STRIDE + oc0 + 4);
            #pragma unroll
            for (int i = 0; i < 4; i++) {
                float p = Ps[(r0 + i) * PS_STRIDE + j];
                O[i][0] = fmaf(p, v0.x, O[i][0]);
                O[i][1] = fmaf(p, v0.y, O[i][1]);
                O[i][2] = fmaf(p, v0.z, O[i][2]);
                O[i][3] = fmaf(p, v0.w, O[i][3]);
                O[i][4] = fmaf(p, v1.x, O[i][4]);
                O[i][5] = fmaf(p, v1.y, O[i][5]);
                O[i][6] = fmaf(p, v1.z, O[i][6]);
                O[i][7] = fmaf(p, v1.w, O[i][7]);
            }
        }
    }

    // Normalize, round to tf32 (feeds Wo MMA), write out
    #pragma unroll
    for (int i = 0; i < 4; i++) {
        float inv = 1.0f / l_i[i];
        float* op = g_att + (size_t)(qt * 64 + r0 + i) * DMODEL + h * HD + oc0;
        *(float4*)(op)     = make_float4(tf32r(O[i][0]*inv), tf32r(O[i][1]*inv),
                                         tf32r(O[i][2]*inv), tf32r(O[i][3]*inv));
        *(float4*)(op + 4) = make_float4(tf32r(O[i][4]*inv), tf32r(O[i][5]*inv),
                                         tf32r(O[i][6]*inv), tf32r(O[i][7]*inv));
    }
}

// ---------------------------------------------------------------------------
extern "C" void kernel_launch(void* const* d_in, const int* in_sizes, int n_in,
                              void* d_out, int out_size)
{
    const float* X    = (const float*)d_in[0];
    const float* cosT = (const float*)d_in[1];
    const float* sinT = (const float*)d_in[2];
    const float* Wq   = (const float*)d_in[3];
    const float* Wk   = (const float*)d_in[4];
    const float* Wv   = (const float*)d_in[5];
    const float* Wo   = (const float*)d_in[6];
    float* out = (float*)d_out;

    float *pq, *pk, *pv, *pa, *pxr, *pwqt, *pwkt, *pwvt, *pwot;
    cudaGetSymbolAddress((void**)&pq,   g_q);
    cudaGetSymbolAddress((void**)&pk,   g_k);
    cudaGetSymbolAddress((void**)&pv,   g_v);
    cudaGetSymbolAddress((void**)&pa,   g_att);
    cudaGetSymbolAddress((void**)&pxr,  g_xr);
    cudaGetSymbolAddress((void**)&pwqt, g_wqt);
    cudaGetSymbolAddress((void**)&pwkt, g_wkt);
    cudaGetSymbolAddress((void**)&pwvt, g_wvt);
    cudaGetSymbolAddress((void**)&pwot, g_wot);

    cudaFuncSetAttribute(attn_kernel, cudaFuncAttributeMaxDynamicSharedMemorySize,
                         ATT_SMEM_FLOATS * (int)sizeof(float));
    cudaFuncSetAttribute(mma_gemm_tf32, cudaFuncAttributeMaxDynamicSharedMemorySize,
                         GEMM_SMEM);

    dim3 tb(32, 8);
    transpose_round_kernel<<<dim3(DMODEL/32, DMODEL/32), tb>>>(Wq, pwqt, DMODEL, DMODEL);
    transpose_round_kernel<<<dim3(KV_DIM/32, DMODEL/32), tb>>>(Wk, pwkt, DMODEL, KV_DIM);
    transpose_round_kernel<<<dim3(KV_DIM/32, DMODEL/32), tb>>>(Wv, pwvt, DMODEL, KV_DIM);
    transpose_round_kernel<<<dim3(DMODEL/32, DMODEL/32), tb>>>(Wo, pwot, DMODEL, DMODEL);
    {
        int n4 = S_LEN * DMODEL / 4;
        round_x_kernel<<<(n4 + 255) / 256, 256>>>((const float4*)X, (float4*)pxr, n4);
    }

    // QKV projections (mma.sync tf32)
    mma_gemm_tf32<<<dim3(DMODEL/128, S_LEN/128), 256, GEMM_SMEM>>>(pxr, pwqt, pq, DMODEL, DMODEL);
    mma_gemm_tf32<<<dim3(KV_DIM/128, S_LEN/128), 256, GEMM_SMEM>>>(pxr, pwkt, pk, DMODEL, KV_DIM);
    mma_gemm_tf32<<<dim3(KV_DIM/128, S_LEN/128), 256, GEMM_SMEM>>>(pxr, pwvt, pv, DMODEL, KV_DIM);

    // RoPE
    {
        int total = S_LEN * NH * 64 + S_LEN * NKV * 64;
        rope_kernel<<<(total + 255) / 256, 256>>>(cosT, sinT);
    }

    // Attention (SIMT fp32)
    attn_kernel<<<dim3(S_LEN / 64, NH), 256, ATT_SMEM_FLOATS * (int)sizeof(float)>>>();

    // Output projection (mma.sync tf32)
    mma_gemm_tf32<<<dim3(DMODEL/128, S_LEN/128), 256, GEMM_SMEM>>>(pa, pwot, out, DMODEL, DMODEL);
}